// round 10
// baseline (speedup 1.0000x reference)
#include <cuda_runtime.h>

#define BATCH  16384
#define NNZ    819200
#define KDIM   16
#define VOCAB  1000000
#define RPW    2          // rows per warp (consecutive -> contiguous nnz)
#define CAP    192        // staged nnz per chunk (span avg ~100, sd ~10)

__device__ int g_row_ptr[BATCH + 1];
__device__ int g_is64;

// ---------------------------------------------------------------------------
// dtype detection: words 2i+1 (i < NNZ/2) are in-bounds under both views.
// int64 view -> high words all 0; int32 view -> sorted index vals ~8191 != 0.
// ---------------------------------------------------------------------------
__device__ __forceinline__ int detect_is64(const unsigned int* __restrict__ w) {
    unsigned int acc = 0;
    int base = NNZ / 2 - 8;
#pragma unroll
    for (int i = 0; i < 8; i++) acc |= w[2 * (base + i) + 1];
    return (acc == 0u) ? 1 : 0;
}

template <bool IS64>
__device__ __forceinline__ int ld_i(const void* __restrict__ p, int i) {
    if (IS64) return (int)__ldg((const long long*)p + i);
    return __ldg((const int*)p + i);
}

__device__ __forceinline__ float warp_sum(float r) {
#pragma unroll
    for (int o = 16; o > 0; o >>= 1)
        r += __shfl_xor_sync(0xffffffffu, r, o);
    return r;
}

// ---------------------------------------------------------------------------
// K1: rowptr via adjacent difference over the sorted index (one coalesced
// pass, fully parallel; ~1 us incl. launch).
// ---------------------------------------------------------------------------
__global__ void __launch_bounds__(256)
rowptr_kernel(const void* __restrict__ index) {
    __shared__ int s_is64;
    if (threadIdx.x == 0) {
        int is64 = detect_is64((const unsigned int*)index);
        s_is64 = is64;
        if (blockIdx.x == 0) g_is64 = is64;
    }
    __syncthreads();
    const int is64 = s_is64;

    const int i = blockIdx.x * blockDim.x + threadIdx.x;
    if (i >= NNZ) return;

    int a, b;
    if (is64) {
        a = ld_i<true >(index, i);
        b = (i + 1 < NNZ) ? ld_i<true >(index, i + 1) : BATCH;
    } else {
        a = ld_i<false>(index, i);
        b = (i + 1 < NNZ) ? ld_i<false>(index, i + 1) : BATCH;
    }
    if (i == 0)
        for (int r = 0; r <= a; r++) g_row_ptr[r] = 0;
    for (int r = a + 1; r <= b; r++) g_row_ptr[r] = i + 1;
}

// ---------------------------------------------------------------------------
// K2: warp per 2 consecutive rows. Their nnz are contiguous: one coalesced
// staging pass (feat*16, value) -> smem per chunk. Gather phase per row:
// octet layout (8 groups g x 4 slots m); iteration t = LDS.64 broadcast +
// embedding LDG.128 + (m==0) weights LDG.32 -- all independent, unroll 4.
// Accumulators persist across chunks; one shuffle epilogue per row at end.
// ---------------------------------------------------------------------------
struct __align__(16) WBuf { float2 fv[CAP]; };   // 1.5 KB/warp

template <bool IS64>
__device__ __forceinline__ void fm_pair(
        int b0, int lane, WBuf* __restrict__ buf,
        const void* __restrict__ feats,
        const float* __restrict__ values,
        const float* __restrict__ weights,
        const float* __restrict__ embedding,
        float bias_v, float* __restrict__ out) {
    const int g = lane >> 2;   // octet position 0..7
    const int m = lane & 3;    // float4 slot: k = 4m .. 4m+3

    int se = 0;
    if (lane <= RPW) se = __ldg(&g_row_ptr[b0 + lane]);
    const int s0 = __shfl_sync(0xffffffffu, se, 0);
    const int s1 = __shfl_sync(0xffffffffu, se, 1);
    const int s2 = __shfl_sync(0xffffffffu, se, 2);

    float4 t1a = make_float4(0.f, 0.f, 0.f, 0.f);
    float4 t1b = make_float4(0.f, 0.f, 0.f, 0.f);
    float  t2a = 0.f, t2b = 0.f, fia = 0.f, fib = 0.f;

    for (int cb = s0; cb < s2; cb += CAP) {
        const int n = min(s2 - cb, CAP);

        // ---- stage chunk (single-hop, coalesced) ----
        for (int o = lane; o < n; o += 32) {
            const int   f = ld_i<IS64>(feats, cb + o);
            const float v = __ldg(values + cb + o);
            buf->fv[o] = make_float2(__int_as_float(f * KDIM), v);
        }
        __syncwarp();

        // ---- row 0 slice of this chunk ----
        {
            const int rs = (s0 > cb) ? (s0 - cb) : 0;
            const int re = min(s1, cb + n) - cb;
            const int len = re - rs;
#pragma unroll 4
            for (int t = 0; t < (len + 7) / 8; t++) {
                const int j  = rs + 8 * t + g;
                const int jc = (j < re) ? j : (re - 1);
                const float2 fv = buf->fv[jc];
                const int    fr = __float_as_int(fv.x);
                const float  vv = (j < re) ? fv.y : 0.f;
                const float4 e4 = __ldg((const float4*)(embedding + fr) + m);
                if (m == 0) fia = fmaf(__ldg(weights + (fr >> 4)), vv, fia);
                const float e0 = e4.x * vv, e1 = e4.y * vv,
                            e2 = e4.z * vv, e3 = e4.w * vv;
                t1a.x += e0; t1a.y += e1; t1a.z += e2; t1a.w += e3;
                t2a = fmaf(e0, e0, t2a); t2a = fmaf(e1, e1, t2a);
                t2a = fmaf(e2, e2, t2a); t2a = fmaf(e3, e3, t2a);
            }
        }
        // ---- row 1 slice of this chunk ----
        {
            const int rs = (s1 > cb) ? (s1 - cb) : 0;
            const int re = min(s2, cb + n) - cb;
            const int len = re - rs;
#pragma unroll 4
            for (int t = 0; t < (len + 7) / 8; t++) {
                const int j  = rs + 8 * t + g;
                const int jc = (j < re) ? j : (re - 1);
                const float2 fv = buf->fv[jc];
                const int    fr = __float_as_int(fv.x);
                const float  vv = (j < re) ? fv.y : 0.f;
                const float4 e4 = __ldg((const float4*)(embedding + fr) + m);
                if (m == 0) fib = fmaf(__ldg(weights + (fr >> 4)), vv, fib);
                const float e0 = e4.x * vv, e1 = e4.y * vv,
                            e2 = e4.z * vv, e3 = e4.w * vv;
                t1b.x += e0; t1b.y += e1; t1b.z += e2; t1b.w += e3;
                t2b = fmaf(e0, e0, t2b); t2b = fmaf(e1, e1, t2b);
                t2b = fmaf(e2, e2, t2b); t2b = fmaf(e3, e3, t2b);
            }
        }
        __syncwarp();
    }

    // ---- epilogues (octet combine over lane bits 2..4, then warp sum) ----
#pragma unroll
    for (int o = 4; o <= 16; o <<= 1) {
        t1a.x += __shfl_xor_sync(0xffffffffu, t1a.x, o);
        t1a.y += __shfl_xor_sync(0xffffffffu, t1a.y, o);
        t1a.z += __shfl_xor_sync(0xffffffffu, t1a.z, o);
        t1a.w += __shfl_xor_sync(0xffffffffu, t1a.w, o);
        t1b.x += __shfl_xor_sync(0xffffffffu, t1b.x, o);
        t1b.y += __shfl_xor_sync(0xffffffffu, t1b.y, o);
        t1b.z += __shfl_xor_sync(0xffffffffu, t1b.z, o);
        t1b.w += __shfl_xor_sync(0xffffffffu, t1b.w, o);
    }
    // |t1|^2 replicated 8x across g-groups -> coefficient 0.5/8 = 0.0625
    float ra = 0.0625f * (t1a.x * t1a.x + t1a.y * t1a.y + t1a.z * t1a.z + t1a.w * t1a.w)
             - 0.5f * t2a + fia;
    float rb = 0.0625f * (t1b.x * t1b.x + t1b.y * t1b.y + t1b.z * t1b.z + t1b.w * t1b.w)
             - 0.5f * t2b + fib;
    ra = warp_sum(ra);
    rb = warp_sum(rb);

    if (lane == 0) {
        out[b0]     = 1.0f / (1.0f + expf(-(ra + bias_v)));
        out[b0 + 1] = 1.0f / (1.0f + expf(-(rb + bias_v)));
    }
}

__global__ void __launch_bounds__(256)
fm_kernel(const void* __restrict__ feats,
          const float* __restrict__ values,
          const float* __restrict__ weights,
          const float* __restrict__ embedding,
          const float* __restrict__ bias,
          float* __restrict__ out) {
    __shared__ WBuf bufs[8];

    const int warp = (blockIdx.x * blockDim.x + threadIdx.x) >> 5;
    const int lane = threadIdx.x & 31;
    if (warp >= BATCH / RPW) return;
    WBuf* buf = &bufs[threadIdx.x >> 5];
    const float bias_v = __ldg(bias);

    if (g_is64) fm_pair<true >(warp * RPW, lane, buf, feats, values, weights, embedding, bias_v, out);
    else        fm_pair<false>(warp * RPW, lane, buf, feats, values, weights, embedding, bias_v, out);
}

// ---------------------------------------------------------------------------
extern "C" void kernel_launch(void* const* d_in, const int* in_sizes, int n_in,
                              void* d_out, int out_size) {
    const void*  index_p   = nullptr;
    const void*  feats_p   = nullptr;
    const float* values_p  = nullptr;
    const float* bias_p    = nullptr;
    const float* weights_p = nullptr;
    const float* embed_p   = nullptr;

    int triple = 0;
    for (int i = 0; i < n_in; i++) {
        int sz = in_sizes[i];
        if (sz == NNZ) {
            if      (triple == 0) index_p  = d_in[i];
            else if (triple == 1) feats_p  = d_in[i];
            else                  values_p = (const float*)d_in[i];
            triple++;
        } else if (sz == VOCAB) {
            weights_p = (const float*)d_in[i];
        } else if (sz == VOCAB * KDIM) {
            embed_p = (const float*)d_in[i];
        } else if (sz == 1) {
            bias_p = (const float*)d_in[i];   // last size-1 input is bias
        }
    }

    float* out = (float*)d_out;
    (void)out_size;

    rowptr_kernel<<<(NNZ + 255) / 256, 256>>>(index_p);
    fm_kernel<<<((BATCH / RPW) * 32 + 255) / 256, 256>>>(feats_p, values_p,
                                                         weights_p, embed_p,
                                                         bias_p, out);
}

// round 12
// speedup vs baseline: 1.0234x; 1.0234x over previous
#include <cuda_runtime.h>

#define BATCH  16384
#define NNZ    819200
#define KDIM   16
#define VOCAB  1000000
#define CAP    256        // staged nnz per super-chunk

__device__ int g_row_ptr[BATCH + 1];
__device__ int g_is64;

// ---------------------------------------------------------------------------
// L2 residency control.
//  Tables (embedding, weights): ld.global.nc.L2::cache_hint with an
//    evict_last fractional policy -> keep resident in L2 across replays.
//  Streams (index/feats/values): __ldcs (ld.global.cs) -> evict-first-ish,
//    don't churn the table out of L2.
// ---------------------------------------------------------------------------
__device__ __forceinline__ unsigned long long policy_evict_last() {
    unsigned long long p;
    asm("createpolicy.fractional.L2::evict_last.b64 %0, 1.0;" : "=l"(p));
    return p;
}
__device__ __forceinline__ float4 ldg_keep_v4(const float* p, unsigned long long pol) {
    float4 r;
    asm("ld.global.nc.L2::cache_hint.v4.f32 {%0,%1,%2,%3}, [%4], %5;"
        : "=f"(r.x), "=f"(r.y), "=f"(r.z), "=f"(r.w) : "l"(p), "l"(pol));
    return r;
}
__device__ __forceinline__ float ldg_keep_f(const float* p, unsigned long long pol) {
    float r;
    asm("ld.global.nc.L2::cache_hint.f32 %0, [%1], %2;" : "=f"(r) : "l"(p), "l"(pol));
    return r;
}

// ---------------------------------------------------------------------------
// dtype detection: words 2i+1 (i < NNZ/2) are in-bounds under both views.
// int64 view -> high words all 0; int32 view -> sorted index vals ~8191 != 0.
// ---------------------------------------------------------------------------
__device__ __forceinline__ int detect_is64(const unsigned int* __restrict__ w) {
    unsigned int acc = 0;
    int base = NNZ / 2 - 8;
#pragma unroll
    for (int i = 0; i < 8; i++) acc |= w[2 * (base + i) + 1];
    return (acc == 0u) ? 1 : 0;
}

template <bool IS64>
__device__ __forceinline__ int ld_i(const void* __restrict__ p, int i) {
    if (IS64) return (int)__ldcs((const long long*)p + i);
    return __ldcs((const int*)p + i);
}

__device__ __forceinline__ float warp_sum(float r) {
#pragma unroll
    for (int o = 16; o > 0; o >>= 1)
        r += __shfl_xor_sync(0xffffffffu, r, o);
    return r;
}

// ---------------------------------------------------------------------------
// K1: rowptr via adjacent difference over the sorted index. One coalesced
// pass, fully parallel.
// ---------------------------------------------------------------------------
__global__ void __launch_bounds__(256)
rowptr_kernel(const void* __restrict__ index) {
    __shared__ int s_is64;
    if (threadIdx.x == 0) {
        int is64 = detect_is64((const unsigned int*)index);
        s_is64 = is64;
        if (blockIdx.x == 0) g_is64 = is64;
    }
    __syncthreads();
    const int is64 = s_is64;

    const int i = blockIdx.x * blockDim.x + threadIdx.x;
    if (i >= NNZ) return;

    int a, b;
    if (is64) {
        a = ld_i<true >(index, i);
        b = (i + 1 < NNZ) ? ld_i<true >(index, i + 1) : BATCH;
    } else {
        a = ld_i<false>(index, i);
        b = (i + 1 < NNZ) ? ld_i<false>(index, i + 1) : BATCH;
    }
    if (i == 0)
        for (int r = 0; r <= a; r++) g_row_ptr[r] = 0;
    for (int r = a + 1; r <= b; r++) g_row_ptr[r] = i + 1;
}

// ---------------------------------------------------------------------------
// K2: warp per row (R9 structure; only the load cache-policies changed).
//  Phase 1 (stage): coalesced (feat*16, value) -> smem, padded to x8;
//    first-order gather folded in (evict_last policy on weights).
//  Phase 2 (gather): octet layout (8 groups g x 4 slots m); LDS.64 broadcast
//    + embedding LDG.128 with evict_last policy; independent iters, unroll 4.
// ---------------------------------------------------------------------------
struct __align__(16) WBuf { float2 fv[CAP]; };   // 2 KB/warp

template <bool IS64>
__device__ __forceinline__ float fm_row(
        int s, int e, int lane, WBuf* __restrict__ buf,
        const void* __restrict__ feats,
        const float* __restrict__ values,
        const float* __restrict__ weights,
        const float* __restrict__ embedding,
        unsigned long long pol) {
    const int g = lane >> 2;   // octet position 0..7
    const int m = lane & 3;    // float4 slot: k = 4m .. 4m+3

    float4 t1 = make_float4(0.f, 0.f, 0.f, 0.f);
    float  t2 = 0.f, first = 0.f;

    for (int base = s; base < e; base += CAP) {
        const int n    = min(e - base, CAP);
        const int npad = (n + 7) & ~7;

        // ---- stage (coalesced); fold first-order gather in ----
        for (int o = lane; o < npad; o += 32) {
            int   f = 0;
            float v = 0.f;
            if (o < n) {
                f = ld_i<IS64>(feats, base + o);
                v = __ldcs(values + base + o);
                first += ldg_keep_f(weights + f, pol) * v;
            }
            buf->fv[o] = make_float2(__int_as_float(f * KDIM), v);
        }
        __syncwarp();

        // ---- gather: independent iterations, deep MLP ----
        const int iters = npad >> 3;
#pragma unroll 4
        for (int t = 0; t < iters; t++) {
            const float2 fv  = buf->fv[8 * t + g];     // 4-lane broadcast
            const int    fr  = __float_as_int(fv.x);
            const float  vv  = fv.y;
            const float4 e4  = ldg_keep_v4(embedding + fr + 4 * m, pol);
            const float e0 = e4.x * vv, e1 = e4.y * vv,
                        e2 = e4.z * vv, e3 = e4.w * vv;
            t1.x += e0; t1.y += e1; t1.z += e2; t1.w += e3;
            t2 = fmaf(e0, e0, t2); t2 = fmaf(e1, e1, t2);
            t2 = fmaf(e2, e2, t2); t2 = fmaf(e3, e3, t2);
        }
        __syncwarp();
    }

    // reduce t1 over the 8 octet-groups (lane bits 2..4)
#pragma unroll
    for (int o = 4; o <= 16; o <<= 1) {
        t1.x += __shfl_xor_sync(0xffffffffu, t1.x, o);
        t1.y += __shfl_xor_sync(0xffffffffu, t1.y, o);
        t1.z += __shfl_xor_sync(0xffffffffu, t1.z, o);
        t1.w += __shfl_xor_sync(0xffffffffu, t1.w, o);
    }

    // |t1|^2 replicated 8x across g-groups -> coefficient 0.5/8 = 0.0625
    float r = 0.0625f * (t1.x * t1.x + t1.y * t1.y + t1.z * t1.z + t1.w * t1.w)
            - 0.5f * t2 + first;
    return warp_sum(r);
}

__global__ void __launch_bounds__(256)
fm_kernel(const void* __restrict__ feats,
          const float* __restrict__ values,
          const float* __restrict__ weights,
          const float* __restrict__ embedding,
          const float* __restrict__ bias,
          float* __restrict__ out) {
    __shared__ WBuf bufs[8];

    const int warp = (blockIdx.x * blockDim.x + threadIdx.x) >> 5;
    const int lane = threadIdx.x & 31;
    if (warp >= BATCH) return;
    const int b = warp;
    WBuf* buf = &bufs[threadIdx.x >> 5];
    const unsigned long long pol = policy_evict_last();

    const int s = g_row_ptr[b];
    const int e = g_row_ptr[b + 1];

    float r = 0.f;
    if (e > s) {
        if (g_is64) r = fm_row<true >(s, e, lane, buf, feats, values, weights, embedding, pol);
        else        r = fm_row<false>(s, e, lane, buf, feats, values, weights, embedding, pol);
    }

    if (lane == 0) {
        const float x = r + __ldg(bias);
        out[b] = 1.0f / (1.0f + expf(-x));
    }
}

// ---------------------------------------------------------------------------
extern "C" void kernel_launch(void* const* d_in, const int* in_sizes, int n_in,
                              void* d_out, int out_size) {
    const void*  index_p   = nullptr;
    const void*  feats_p   = nullptr;
    const float* values_p  = nullptr;
    const float* bias_p    = nullptr;
    const float* weights_p = nullptr;
    const float* embed_p   = nullptr;

    int triple = 0;
    for (int i = 0; i < n_in; i++) {
        int sz = in_sizes[i];
        if (sz == NNZ) {
            if      (triple == 0) index_p  = d_in[i];
            else if (triple == 1) feats_p  = d_in[i];
            else                  values_p = (const float*)d_in[i];
            triple++;
        } else if (sz == VOCAB) {
            weights_p = (const float*)d_in[i];
        } else if (sz == VOCAB * KDIM) {
            embed_p = (const float*)d_in[i];
        } else if (sz == 1) {
            bias_p = (const float*)d_in[i];   // last size-1 input is bias
        }
    }

    float* out = (float*)d_out;
    (void)out_size;

    rowptr_kernel<<<(NNZ + 255) / 256, 256>>>(index_p);
    fm_kernel<<<(BATCH * 32 + 255) / 256, 256>>>(feats_p, values_p, weights_p,
                                                 embed_p, bias_p, out);
}

// round 16
// speedup vs baseline: 1.0615x; 1.0372x over previous
#include <cuda_runtime.h>

#define BATCH  16384
#define NNZ    819200
#define KDIM   16
#define VOCAB  1000000
#define CAP    96          // one chunk covers ~all rows (avg 50, max ~90)

__device__ int g_row_ptr[BATCH + 1];
__device__ int g_is64;

// ---------------------------------------------------------------------------
// dtype detection: words 2i+1 (i < NNZ/2) are in-bounds under both views.
// int64 view -> high words all 0; int32 view -> sorted index vals ~8191 != 0.
// ---------------------------------------------------------------------------
__device__ __forceinline__ int detect_is64(const unsigned int* __restrict__ w) {
    unsigned int acc = 0;
    int base = NNZ / 2 - 8;
#pragma unroll
    for (int i = 0; i < 8; i++) acc |= w[2 * (base + i) + 1];
    return (acc == 0u) ? 1 : 0;
}

template <bool IS64>
__device__ __forceinline__ int ld_i(const void* __restrict__ p, int i) {
    if (IS64) return (int)__ldcs((const long long*)p + i);
    return __ldcs((const int*)p + i);
}

__device__ __forceinline__ float warp_sum(float r) {
#pragma unroll
    for (int o = 16; o > 0; o >>= 1)
        r += __shfl_xor_sync(0xffffffffu, r, o);
    return r;
}

// ---------------------------------------------------------------------------
// K1: rowptr via adjacent difference over the sorted index (proven ~1 us).
// ---------------------------------------------------------------------------
__global__ void __launch_bounds__(256)
rowptr_kernel(const void* __restrict__ index) {
    __shared__ int s_is64;
    if (threadIdx.x == 0) {
        int is64 = detect_is64((const unsigned int*)index);
        s_is64 = is64;
        if (blockIdx.x == 0) g_is64 = is64;
    }
    __syncthreads();
    const int is64 = s_is64;

    const int i = blockIdx.x * blockDim.x + threadIdx.x;
    if (i >= NNZ) return;

    int a, b;
    if (is64) {
        a = ld_i<true >(index, i);
        b = (i + 1 < NNZ) ? ld_i<true >(index, i + 1) : BATCH;
    } else {
        a = ld_i<false>(index, i);
        b = (i + 1 < NNZ) ? ld_i<false>(index, i + 1) : BATCH;
    }
    if (i == 0)
        for (int r = 0; r <= a; r++) g_row_ptr[r] = 0;
    for (int r = a + 1; r <= b; r++) g_row_ptr[r] = i + 1;
}

// ---------------------------------------------------------------------------
// K2: warp per row.
//  Stage: 3 explicit predicated slots (CAP=96) -- all feats/values loads
//    issue back-to-back, then 3 independent weights loads, then unconditional
//    smem stores (zero padding), and the `first` FMA chain LAST so no load
//    latency gates the loop or the gather phase.
//  Gather: octet layout (8 groups g x 4 slots m); LDS.64 broadcast +
//    embedding LDG.128; independent iterations, unroll 4.
// ---------------------------------------------------------------------------
struct __align__(16) WBuf { float2 fv[CAP]; };   // 768 B/warp

template <bool IS64>
__device__ __forceinline__ float fm_row(
        int s, int e, int lane, WBuf* __restrict__ buf,
        const void* __restrict__ feats,
        const float* __restrict__ values,
        const float* __restrict__ weights,
        const float* __restrict__ embedding) {
    const int g = lane >> 2;   // octet position 0..7
    const int m = lane & 3;    // float4 slot: k = 4m .. 4m+3

    float4 t1 = make_float4(0.f, 0.f, 0.f, 0.f);
    float  t2 = 0.f, first = 0.f;

    for (int base = s; base < e; base += CAP) {
        const int n = min(e - base, CAP);

        // ---- stage: flattened 3-slot form, loads first, FMAs last ----
        const int o0 = lane, o1 = lane + 32, o2 = lane + 64;
        int   f0 = 0, f1 = 0, f2 = 0;
        float v0 = 0.f, v1 = 0.f, v2 = 0.f;
        if (o0 < n) { f0 = ld_i<IS64>(feats, base + o0); v0 = __ldcs(values + base + o0); }
        if (o1 < n) { f1 = ld_i<IS64>(feats, base + o1); v1 = __ldcs(values + base + o1); }
        if (o2 < n) { f2 = ld_i<IS64>(feats, base + o2); v2 = __ldcs(values + base + o2); }

        float w0 = 0.f, w1 = 0.f, w2 = 0.f;
        if (o0 < n) w0 = __ldg(weights + f0);
        if (o1 < n) w1 = __ldg(weights + f1);
        if (o2 < n) w2 = __ldg(weights + f2);

        buf->fv[o0] = make_float2(__int_as_float(f0 * KDIM), v0);
        buf->fv[o1] = make_float2(__int_as_float(f1 * KDIM), v1);
        buf->fv[o2] = make_float2(__int_as_float(f2 * KDIM), v2);
        __syncwarp();

        // first-order FMAs: consumed only at the epilogue, never gate issue
        first = fmaf(w0, v0, first);
        first = fmaf(w1, v1, first);
        first = fmaf(w2, v2, first);

        // ---- gather: independent iterations, deep MLP ----
        const int iters = (n + 7) >> 3;
#pragma unroll 4
        for (int t = 0; t < iters; t++) {
            const float2 fv = buf->fv[8 * t + g];      // 4-lane broadcast LDS
            const int    fr = __float_as_int(fv.x);
            const float  vv = fv.y;
            const float4 e4 = __ldg((const float4*)(embedding + fr) + m);
            const float e0 = e4.x * vv, e1 = e4.y * vv,
                        e2 = e4.z * vv, e3 = e4.w * vv;
            t1.x += e0; t1.y += e1; t1.z += e2; t1.w += e3;
            t2 = fmaf(e0, e0, t2); t2 = fmaf(e1, e1, t2);
            t2 = fmaf(e2, e2, t2); t2 = fmaf(e3, e3, t2);
        }
        __syncwarp();
    }

    // reduce t1 over the 8 octet-groups (lane bits 2..4)
#pragma unroll
    for (int o = 4; o <= 16; o <<= 1) {
        t1.x += __shfl_xor_sync(0xffffffffu, t1.x, o);
        t1.y += __shfl_xor_sync(0xffffffffu, t1.y, o);
        t1.z += __shfl_xor_sync(0xffffffffu, t1.z, o);
        t1.w += __shfl_xor_sync(0xffffffffu, t1.w, o);
    }

    // |t1|^2 replicated 8x across g-groups -> coefficient 0.5/8 = 0.0625
    float r = 0.0625f * (t1.x * t1.x + t1.y * t1.y + t1.z * t1.z + t1.w * t1.w)
            - 0.5f * t2 + first;
    return warp_sum(r);
}

__global__ void __launch_bounds__(256)
fm_kernel(const void* __restrict__ feats,
          const float* __restrict__ values,
          const float* __restrict__ weights,
          const float* __restrict__ embedding,
          const float* __restrict__ bias,
          float* __restrict__ out) {
    __shared__ WBuf bufs[8];

    const int warp = (blockIdx.x * blockDim.x + threadIdx.x) >> 5;
    const int lane = threadIdx.x & 31;
    if (warp >= BATCH) return;
    const int b = warp;
    WBuf* buf = &bufs[threadIdx.x >> 5];

    const int s = g_row_ptr[b];
    const int e = g_row_ptr[b + 1];

    float r = 0.f;
    if (e > s) {
        if (g_is64) r = fm_row<true >(s, e, lane, buf, feats, values, weights, embedding);
        else        r = fm_row<false>(s, e, lane, buf, feats, values, weights, embedding);
    }

    if (lane == 0) {
        const float x = r + __ldg(bias);
        out[b] = 1.0f / (1.0f + expf(-x));
    }
}

// ---------------------------------------------------------------------------
extern "C" void kernel_launch(void* const* d_in, const int* in_sizes, int n_in,
                              void* d_out, int out_size) {
    const void*  index_p   = nullptr;
    const void*  feats_p   = nullptr;
    const float* values_p  = nullptr;
    const float* bias_p    = nullptr;
    const float* weights_p = nullptr;
    const float* embed_p   = nullptr;

    int triple = 0;
    for (int i = 0; i < n_in; i++) {
        int sz = in_sizes[i];
        if (sz == NNZ) {
            if      (triple == 0) index_p  = d_in[i];
            else if (triple == 1) feats_p  = d_in[i];
            else                  values_p = (const float*)d_in[i];
            triple++;
        } else if (sz == VOCAB) {
            weights_p = (const float*)d_in[i];
        } else if (sz == VOCAB * KDIM) {
            embed_p = (const float*)d_in[i];
        } else if (sz == 1) {
            bias_p = (const float*)d_in[i];   // last size-1 input is bias
        }
    }

    float* out = (float*)d_out;
    (void)out_size;

    rowptr_kernel<<<(NNZ + 255) / 256, 256>>>(index_p);
    fm_kernel<<<(BATCH * 32 + 255) / 256, 256>>>(feats_p, values_p, weights_p,
                                                 embed_p, bias_p, out);
}